// round 12
// baseline (speedup 1.0000x reference)
#include <cuda_runtime.h>
#include <cuda_bf16.h>
#include <math.h>
#include <stdint.h>

#define Bb   32
#define Ss   577
#define Hh   1024
#define NH_  16
#define DH_  64
#define NTOK (Bb*Ss)          // 18464

// ---------------- scratch (__device__ globals; no allocs allowed) ----------
__device__ float g_Q[(size_t)NTOK*Hh];   // head-major [B,NH,S,DH]
__device__ float g_K[(size_t)NTOK*Hh];
__device__ float g_V[(size_t)NTOK*Hh];
__device__ float g_C[(size_t)NTOK*Hh];   // token-major [B,S,H]

__device__ __align__(16) __nv_bfloat16 g_Xh[(size_t)NTOK*Hh];
__device__ __align__(16) __nv_bfloat16 g_Xl[(size_t)NTOK*Hh];
__device__ __align__(16) __nv_bfloat16 g_Ch[(size_t)NTOK*Hh];
__device__ __align__(16) __nv_bfloat16 g_Cl[(size_t)NTOK*Hh];
__device__ __align__(16) __nv_bfloat16 g_Wh[(size_t)4*Hh*Hh];
__device__ __align__(16) __nv_bfloat16 g_Wl[(size_t)4*Hh*Hh];

// ---------------- PTX helpers (sm_80-class only; no 'a'-gated features) ----
__device__ __forceinline__ uint32_t smem_u32(const void* p) {
    uint32_t a;
    asm("{ .reg .u64 t; cvta.to.shared.u64 t, %1; cvt.u32.u64 %0, t; }" : "=r"(a) : "l"(p));
    return a;
}
__device__ __forceinline__ void cp16(uint32_t dst, const void* src, int valid) {
    int sz = valid ? 16 : 0;
    asm volatile("cp.async.cg.shared.global [%0], [%1], 16, %2;"
                 :: "r"(dst), "l"(src), "r"(sz) : "memory");
}
#define CP_COMMIT() asm volatile("cp.async.commit_group;" ::: "memory")
#define CP_WAIT0()  asm volatile("cp.async.wait_group 0;" ::: "memory")
#define CP_WAIT1()  asm volatile("cp.async.wait_group 1;" ::: "memory")

#define LDM4(R, ADDR) \
    asm volatile("ldmatrix.sync.aligned.m8n8.x4.shared.b16 {%0,%1,%2,%3}, [%4];" \
        : "=r"((R)[0]), "=r"((R)[1]), "=r"((R)[2]), "=r"((R)[3]) : "r"(ADDR))

#define MMA16816(D, A, B0, B1) \
    asm volatile("mma.sync.aligned.m16n8k16.row.col.f32.bf16.bf16.f32 " \
        "{%0,%1,%2,%3},{%4,%5,%6,%7},{%8,%9},{%0,%1,%2,%3};" \
        : "+f"((D)[0]), "+f"((D)[1]), "+f"((D)[2]), "+f"((D)[3]) \
        : "r"((A)[0]), "r"((A)[1]), "r"((A)[2]), "r"((A)[3]), "r"(B0), "r"(B1))

// ---------------- split fp32 -> bf16 hi/lo --------------------------------
__global__ __launch_bounds__(256)
void split_k(const float* __restrict__ x, __nv_bfloat16* __restrict__ hi,
             __nv_bfloat16* __restrict__ lo, int n)
{
    int i = (blockIdx.x * 256 + threadIdx.x) * 4;
    if (i >= n) return;
    float4 v = *(const float4*)(x + i);
    float f[4] = {v.x, v.y, v.z, v.w};
    union { __nv_bfloat16 b[4]; uint2 u; } ph, pl;
#pragma unroll
    for (int k = 0; k < 4; k++) {
        __nv_bfloat16 h = __float2bfloat16(f[k]);
        ph.b[k] = h;
        pl.b[k] = __float2bfloat16(f[k] - __bfloat162float(h));
    }
    *(uint2*)(hi + i) = ph.u;
    *(uint2*)(lo + i) = pl.u;
}

// ---------------- HMMA split-bf16 GEMM ------------------------------------
// out[N x 1024] = A @ W^T + bias via 3 bf16 passes (Ah*Wh + Ah*Wl + Al*Wh).
// CTA tile 128x128, K-chunk 32, double-buffered cp.async.
// smem: rows at 80B pitch (5 x 16B units) -> ldmatrix conflict-free
//       (5*r mod 8 permutes 0..7 across the 8 rows of each ldmatrix phase).
// 8 warps = 2 (M) x 4 (N): warp tile 64x32 of m16n8k16 atoms.
// MODE 0: head-major Q/K/V layout; MODE 1: token-major.
#define TILE_B   (128*5*16)           // 10240 B per operand tile
#define SMEM_GEMM (8*TILE_B)          // 2 stages x 4 tiles = 81920 B

template<int MODE>
__global__ __launch_bounds__(256, 1)
void gemm_mma(const __nv_bfloat16* __restrict__ Ah, const __nv_bfloat16* __restrict__ Al,
              const __nv_bfloat16* __restrict__ Wh, const __nv_bfloat16* __restrict__ Wl,
              const float* __restrict__ bias, float* __restrict__ out, int Nrows)
{
    extern __shared__ __align__(128) char smem[];
    const uint32_t sb = smem_u32(smem);
    const int tid  = threadIdx.x;
    const int wid  = tid >> 5;
    const int lane = tid & 31;
    const int n0 = blockIdx.x * 128;
    const int m0 = blockIdx.y * 128;
    const int warp_m = wid & 1;        // 0..1 -> 64 rows each
    const int warp_n = wid >> 1;       // 0..3 -> 32 cols each

    // ---- chunk loader: 4 tiles (Ah,Al,Wh,Wl) of 128 rows x 64B ----
    auto fill = [&](int chunk, int s) {
        const int k0 = chunk * 32;
        const uint32_t base = sb + s * 4 * TILE_B;
        for (int idx = tid; idx < 512; idx += 256) {
            const int r = idx >> 2, c = idx & 3;
            const uint32_t dst = (uint32_t)(r * 5 + c) * 16;
            const int ar = n0 + r;
            const int av = (ar < Nrows);
            const size_t ao = (size_t)(av ? ar : 0) * 1024 + k0 + c * 8;
            cp16(base + dst,              Ah + ao, av);
            cp16(base + TILE_B + dst,     Al + ao, av);
            const size_t wo = (size_t)(m0 + r) * 1024 + k0 + c * 8;
            cp16(base + 2*TILE_B + dst,   Wh + wo, 1);
            cp16(base + 3*TILE_B + dst,   Wl + wo, 1);
        }
    };

    float acc[4][4][4];               // [ma][n8][d0..d3]
#pragma unroll
    for (int i = 0; i < 4; i++)
#pragma unroll
        for (int j = 0; j < 4; j++)
#pragma unroll
            for (int d = 0; d < 4; d++) acc[i][j][d] = 0.f;

    const int rA = warp_m * 64 + (lane & 15);   // + ma*16
    const int rW = warp_n * 32 + (lane & 15);   // + nb16*16

    fill(0, 0); CP_COMMIT();

    for (int ch = 0; ch < 32; ch++) {
        if (ch + 1 < 32) { fill(ch + 1, (ch + 1) & 1); CP_COMMIT(); CP_WAIT1(); }
        else             { CP_WAIT0(); }
        __syncthreads();

        const uint32_t base = sb + (ch & 1) * 4 * TILE_B;
        const uint32_t aHb = base, aLb = base + TILE_B;
        const uint32_t wHb = base + 2*TILE_B, wLb = base + 3*TILE_B;

#pragma unroll
        for (int ks = 0; ks < 2; ks++) {
            const int c16 = ks * 2 + (lane >> 4);
            uint32_t ah[4][4], al[4][4], bh[2][4], bl[2][4];
#pragma unroll
            for (int ma = 0; ma < 4; ma++) {
                const uint32_t off = (uint32_t)((rA + ma*16) * 5 + c16) * 16;
                LDM4(ah[ma], aHb + off);
                LDM4(al[ma], aLb + off);
            }
#pragma unroll
            for (int nb = 0; nb < 2; nb++) {
                const uint32_t off = (uint32_t)((rW + nb*16) * 5 + c16) * 16;
                LDM4(bh[nb], wHb + off);
                LDM4(bl[nb], wLb + off);
            }
#pragma unroll
            for (int ma = 0; ma < 4; ma++)
#pragma unroll
                for (int n8 = 0; n8 < 4; n8++) {
                    const int nb = n8 >> 1, h = n8 & 1;
                    MMA16816(acc[ma][n8], ah[ma], bh[nb][0+h], bh[nb][2+h]);
                    MMA16816(acc[ma][n8], ah[ma], bl[nb][0+h], bl[nb][2+h]);
                    MMA16816(acc[ma][n8], al[ma], bh[nb][0+h], bh[nb][2+h]);
                }
        }
        __syncthreads();
    }

    // ---- epilogue: bias + layout transform, straight from registers ----
    float bias2[4][2];
#pragma unroll
    for (int n8 = 0; n8 < 4; n8++) {
        const int m = m0 + warp_n*32 + n8*8 + (lane & 3)*2;
        bias2[n8][0] = bias[m];
        bias2[n8][1] = bias[m + 1];
    }
#pragma unroll
    for (int ma = 0; ma < 4; ma++)
#pragma unroll
        for (int half = 0; half < 2; half++) {
            const int n = n0 + warp_m*64 + ma*16 + (lane >> 2) + half*8;
            if (n >= Nrows) continue;
#pragma unroll
            for (int n8 = 0; n8 < 4; n8++) {
                const int m = m0 + warp_n*32 + n8*8 + (lane & 3)*2;
                float2 v;
                v.x = acc[ma][n8][2*half + 0] + bias2[n8][0];
                v.y = acc[ma][n8][2*half + 1] + bias2[n8][1];
                if (MODE == 0) {
                    const int b = n / Ss, s = n - b * Ss;
                    const int h = m >> 6, d = m & 63;
                    *(float2*)(out + (((size_t)(b*NH_ + h))*Ss + s)*DH_ + d) = v;
                } else {
                    *(float2*)(out + (size_t)n*1024 + m) = v;
                }
            }
        }
}

// ---------------------------------------------------------------------------
// Flash-style attention (fp32 path, unchanged). Grid (10, 512), 256 threads.
// ---------------------------------------------------------------------------
__global__ __launch_bounds__(256)
void attn_k(const float* __restrict__ mask, float* __restrict__ ctx)
{
    extern __shared__ float sm[];
    float* Qs = sm;               // 4096
    float* KP = sm + 4096;        // 4160 (pitch 65)
    float* Vs = sm + 4096 + 4160; // 4096

    const int bh = blockIdx.y;
    const int b = bh >> 4, h = bh & 15;
    const int q0 = blockIdx.x * 64;
    const int tid = threadIdx.x;
    const int tr = tid >> 4, tc = tid & 15;

    const float* Qg = g_Q + (size_t)bh * Ss * DH_;
    const float* Kg = g_K + (size_t)bh * Ss * DH_;
    const float* Vg = g_V + (size_t)bh * Ss * DH_;
    const float scale = 0.125f;

    for (int i = tid; i < 4096; i += 256) {
        const int r = i >> 6, c = i & 63;
        const int q = q0 + r;
        Qs[i] = (q < Ss) ? Qg[(size_t)q*64 + c] * scale : 0.f;
    }

    float m_i[4], l_i[4], acc[4][4];
#pragma unroll
    for (int i = 0; i < 4; i++) {
        m_i[i] = -1e30f; l_i[i] = 0.f;
#pragma unroll
        for (int j = 0; j < 4; j++) acc[i][j] = 0.f;
    }

    for (int kt = 0; kt < 10; kt++) {
        const int k0 = kt * 64;
        __syncthreads();
        for (int i = tid; i < 4096; i += 256) {
            const int r = i >> 6, c = i & 63;
            const int k = k0 + r;
            const float kv = (k < Ss) ? Kg[(size_t)k*64 + c] : 0.f;
            const float vv = (k < Ss) ? Vg[(size_t)k*64 + c] : 0.f;
            KP[r*65 + c] = kv;
            Vs[i] = vv;
        }
        __syncthreads();

        float s[4][4];
#pragma unroll
        for (int i = 0; i < 4; i++)
#pragma unroll
            for (int j = 0; j < 4; j++) s[i][j] = 0.f;

#pragma unroll 8
        for (int d = 0; d < 64; d++) {
            float a[4], bb2[4];
#pragma unroll
            for (int i = 0; i < 4; i++) a[i]  = Qs[(tr*4+i)*64 + d];
#pragma unroll
            for (int j = 0; j < 4; j++) bb2[j] = KP[(tc*4+j)*65 + d];
#pragma unroll
            for (int i = 0; i < 4; i++)
#pragma unroll
                for (int j = 0; j < 4; j++) s[i][j] = fmaf(a[i], bb2[j], s[i][j]);
        }

        float mk[4]; bool kok[4];
#pragma unroll
        for (int j = 0; j < 4; j++) {
            const int k = k0 + tc*4 + j;
            kok[j] = (k < Ss);
            mk[j] = kok[j] ? mask[b*Ss + k] : 0.f;
        }
#pragma unroll
        for (int i = 0; i < 4; i++)
#pragma unroll
            for (int j = 0; j < 4; j++)
                s[i][j] = kok[j] ? s[i][j]*mk[j] : -1e30f;

#pragma unroll
        for (int i = 0; i < 4; i++) {
            float tm = fmaxf(fmaxf(s[i][0], s[i][1]), fmaxf(s[i][2], s[i][3]));
#pragma unroll
            for (int o = 8; o >= 1; o >>= 1)
                tm = fmaxf(tm, __shfl_xor_sync(0xffffffffu, tm, o, 16));
            const float mn = fmaxf(m_i[i], tm);
            const float corr = __expf(m_i[i] - mn);
            float rs = 0.f;
#pragma unroll
            for (int j = 0; j < 4; j++) {
                const float p = __expf(s[i][j] - mn);
                s[i][j] = p; rs += p;
            }
#pragma unroll
            for (int o = 8; o >= 1; o >>= 1)
                rs += __shfl_xor_sync(0xffffffffu, rs, o, 16);
            l_i[i] = l_i[i]*corr + rs;
            m_i[i] = mn;
#pragma unroll
            for (int j = 0; j < 4; j++) acc[i][j] *= corr;
        }

        __syncthreads();
#pragma unroll
        for (int i = 0; i < 4; i++)
#pragma unroll
            for (int j = 0; j < 4; j++)
                KP[(tr*4+i)*65 + tc*4 + j] = s[i][j];
        __syncthreads();

#pragma unroll 8
        for (int kk = 0; kk < 64; kk++) {
            float pa[4];
#pragma unroll
            for (int i = 0; i < 4; i++) pa[i] = KP[(tr*4+i)*65 + kk];
            const float4 v4 = *(const float4*)&Vs[kk*64 + tc*4];
            const float vb[4] = {v4.x, v4.y, v4.z, v4.w};
#pragma unroll
            for (int i = 0; i < 4; i++)
#pragma unroll
                for (int j = 0; j < 4; j++) acc[i][j] = fmaf(pa[i], vb[j], acc[i][j]);
        }
    }

#pragma unroll
    for (int i = 0; i < 4; i++) {
        const int q = q0 + tr*4 + i;
        if (q >= Ss) continue;
        const float inv = 1.f / l_i[i];
#pragma unroll
        for (int j = 0; j < 4; j++)
            ctx[((size_t)(b*Ss + q))*Hh + h*64 + tc*4 + j] = acc[i][j]*inv;
    }
}

// ---------------------------------------------------------------------------
extern "C" void kernel_launch(void* const* d_in, const int* in_sizes, int n_in,
                              void* d_out, int out_size)
{
    const float* X    = (const float*)d_in[0];
    const float* mask = (const float*)d_in[1];
    const float* Wq   = (const float*)d_in[2];
    const float* bq   = (const float*)d_in[3];
    const float* Wk   = (const float*)d_in[4];
    const float* bk   = (const float*)d_in[5];
    const float* Wv   = (const float*)d_in[6];
    const float* bv   = (const float*)d_in[7];
    const float* Wo   = (const float*)d_in[8];
    const float* bo   = (const float*)d_in[9];
    float* out = (float*)d_out;

    float *Qp, *Kp, *Vp, *Cp;
    __nv_bfloat16 *Xh, *Xl, *Ch, *Cl, *Wh, *Wl;
    cudaGetSymbolAddress((void**)&Qp, g_Q);
    cudaGetSymbolAddress((void**)&Kp, g_K);
    cudaGetSymbolAddress((void**)&Vp, g_V);
    cudaGetSymbolAddress((void**)&Cp, g_C);
    cudaGetSymbolAddress((void**)&Xh, g_Xh);
    cudaGetSymbolAddress((void**)&Xl, g_Xl);
    cudaGetSymbolAddress((void**)&Ch, g_Ch);
    cudaGetSymbolAddress((void**)&Cl, g_Cl);
    cudaGetSymbolAddress((void**)&Wh, g_Wh);
    cudaGetSymbolAddress((void**)&Wl, g_Wl);

    static bool attr_done = false;
    if (!attr_done) {
        cudaFuncSetAttribute(gemm_mma<0>, cudaFuncAttributeMaxDynamicSharedMemorySize, SMEM_GEMM);
        cudaFuncSetAttribute(gemm_mma<1>, cudaFuncAttributeMaxDynamicSharedMemorySize, SMEM_GEMM);
        cudaFuncSetAttribute(attn_k, cudaFuncAttributeMaxDynamicSharedMemorySize,
                             (4096 + 4160 + 4096) * (int)sizeof(float));
        attr_done = true;
    }

    // split inputs to bf16 hi/lo
    split_k<<<NTOK, 256>>>(X, Xh, Xl, NTOK * Hh);
    const float* Ws[4] = {Wq, Wk, Wv, Wo};
    for (int w = 0; w < 4; w++)
        split_k<<<1024, 256>>>(Ws[w], Wh + (size_t)w*Hh*Hh, Wl + (size_t)w*Hh*Hh, Hh*Hh);

    const dim3 gg((NTOK + 127) / 128, Hh / 128);
    gemm_mma<0><<<gg, 256, SMEM_GEMM>>>(Xh, Xl, Wh + 0*(size_t)Hh*Hh, Wl + 0*(size_t)Hh*Hh, bq, Qp, NTOK);
    gemm_mma<0><<<gg, 256, SMEM_GEMM>>>(Xh, Xl, Wh + 1*(size_t)Hh*Hh, Wl + 1*(size_t)Hh*Hh, bk, Kp, NTOK);
    gemm_mma<0><<<gg, 256, SMEM_GEMM>>>(Xh, Xl, Wh + 2*(size_t)Hh*Hh, Wl + 2*(size_t)Hh*Hh, bv, Vp, NTOK);

    const int smem_attn = (4096 + 4160 + 4096) * (int)sizeof(float);
    attn_k<<<dim3((Ss + 63) / 64, Bb * NH_), 256, smem_attn>>>(mask, Cp);

    split_k<<<NTOK, 256>>>(Cp, Ch, Cl, NTOK * Hh);
    gemm_mma<1><<<gg, 256, SMEM_GEMM>>>(Ch, Cl, Wh + 3*(size_t)Hh*Hh, Wl + 3*(size_t)Hh*Hh, bo, out, NTOK);
}

// round 13
// speedup vs baseline: 1.5321x; 1.5321x over previous
#include <cuda_runtime.h>
#include <cuda_bf16.h>
#include <math.h>
#include <stdint.h>

#define Bb   32
#define Ss   577
#define Hh   1024
#define NH_  16
#define DH_  64
#define NTOK (Bb*Ss)          // 18464

// ---------------- scratch (__device__ globals; no allocs allowed) ----------
__device__ __align__(16) __nv_bfloat16 g_Xh[(size_t)NTOK*Hh];
__device__ __align__(16) __nv_bfloat16 g_Xl[(size_t)NTOK*Hh];
__device__ __align__(16) __nv_bfloat16 g_Wh[(size_t)4*Hh*Hh];
__device__ __align__(16) __nv_bfloat16 g_Wl[(size_t)4*Hh*Hh];
// head-major [B,NH,S,DH] bf16 hi/lo
__device__ __align__(16) __nv_bfloat16 g_Qh[(size_t)NTOK*Hh];
__device__ __align__(16) __nv_bfloat16 g_Ql[(size_t)NTOK*Hh];
__device__ __align__(16) __nv_bfloat16 g_Kh[(size_t)NTOK*Hh];
__device__ __align__(16) __nv_bfloat16 g_Kl[(size_t)NTOK*Hh];
__device__ __align__(16) __nv_bfloat16 g_Vh[(size_t)NTOK*Hh];
__device__ __align__(16) __nv_bfloat16 g_Vl[(size_t)NTOK*Hh];
// token-major [B,S,H] bf16 hi/lo (attention output)
__device__ __align__(16) __nv_bfloat16 g_Ch[(size_t)NTOK*Hh];
__device__ __align__(16) __nv_bfloat16 g_Cl[(size_t)NTOK*Hh];

// ---------------- PTX helpers (sm_80-class only; no 'a'-gated features) ----
__device__ __forceinline__ uint32_t smem_u32(const void* p) {
    uint32_t a;
    asm("{ .reg .u64 t; cvta.to.shared.u64 t, %1; cvt.u32.u64 %0, t; }" : "=r"(a) : "l"(p));
    return a;
}
__device__ __forceinline__ void cp16(uint32_t dst, const void* src, int valid) {
    int sz = valid ? 16 : 0;
    asm volatile("cp.async.cg.shared.global [%0], [%1], 16, %2;"
                 :: "r"(dst), "l"(src), "r"(sz) : "memory");
}
#define CP_COMMIT() asm volatile("cp.async.commit_group;" ::: "memory")
#define CP_WAIT0()  asm volatile("cp.async.wait_group 0;" ::: "memory")
#define CP_WAIT1()  asm volatile("cp.async.wait_group 1;" ::: "memory")

#define LDM4(R, ADDR) \
    asm volatile("ldmatrix.sync.aligned.m8n8.x4.shared.b16 {%0,%1,%2,%3}, [%4];" \
        : "=r"((R)[0]), "=r"((R)[1]), "=r"((R)[2]), "=r"((R)[3]) : "r"(ADDR))
#define LDM4T(R, ADDR) \
    asm volatile("ldmatrix.sync.aligned.m8n8.x4.trans.shared.b16 {%0,%1,%2,%3}, [%4];" \
        : "=r"((R)[0]), "=r"((R)[1]), "=r"((R)[2]), "=r"((R)[3]) : "r"(ADDR))

#define MMA16816(D, A, B0, B1) \
    asm volatile("mma.sync.aligned.m16n8k16.row.col.f32.bf16.bf16.f32 " \
        "{%0,%1,%2,%3},{%4,%5,%6,%7},{%8,%9},{%0,%1,%2,%3};" \
        : "+f"((D)[0]), "+f"((D)[1]), "+f"((D)[2]), "+f"((D)[3]) \
        : "r"((A)[0]), "r"((A)[1]), "r"((A)[2]), "r"((A)[3]), "r"(B0), "r"(B1))

__device__ __forceinline__ uint32_t pack_bf16(float lo, float hi) {
    __nv_bfloat162 t = __float22bfloat162_rn(make_float2(lo, hi));
    return *(uint32_t*)&t;
}
__device__ __forceinline__ float bf16_res(float x) {
    return x - __bfloat162float(__float2bfloat16(x));
}

// ---------------- split fp32 -> bf16 hi/lo --------------------------------
__global__ __launch_bounds__(256)
void split_k(const float* __restrict__ x, __nv_bfloat16* __restrict__ hi,
             __nv_bfloat16* __restrict__ lo, int n)
{
    int i = (blockIdx.x * 256 + threadIdx.x) * 4;
    if (i >= n) return;
    float4 v = *(const float4*)(x + i);
    float f[4] = {v.x, v.y, v.z, v.w};
    union { __nv_bfloat16 b[4]; uint2 u; } ph, pl;
#pragma unroll
    for (int k = 0; k < 4; k++) {
        __nv_bfloat16 h = __float2bfloat16(f[k]);
        ph.b[k] = h;
        pl.b[k] = __float2bfloat16(f[k] - __bfloat162float(h));
    }
    *(uint2*)(hi + i) = ph.u;
    *(uint2*)(lo + i) = pl.u;
}

// ---------------- HMMA split-bf16 GEMM ------------------------------------
// out = A @ W^T + bias via 3 bf16 passes. CTA tile 128x128, K-chunk 32.
// MODE 0: writes bf16 hi/lo head-major (scaled);  MODE 1: fp32 token-major.
#define TILE_B   (128*5*16)           // 10240 B per operand tile
#define SMEM_GEMM (8*TILE_B)          // 81920 B

template<int MODE>
__global__ __launch_bounds__(256, 1)
void gemm_mma(const __nv_bfloat16* __restrict__ Ah, const __nv_bfloat16* __restrict__ Al,
              const __nv_bfloat16* __restrict__ Wh, const __nv_bfloat16* __restrict__ Wl,
              const float* __restrict__ bias,
              __nv_bfloat16* __restrict__ outh, __nv_bfloat16* __restrict__ outl,
              float* __restrict__ outf, float scale, int Nrows)
{
    extern __shared__ __align__(128) char smem[];
    const uint32_t sb = smem_u32(smem);
    const int tid  = threadIdx.x;
    const int wid  = tid >> 5;
    const int lane = tid & 31;
    const int n0 = blockIdx.x * 128;
    const int m0 = blockIdx.y * 128;
    const int warp_m = wid & 1;
    const int warp_n = wid >> 1;

    auto fill = [&](int chunk, int s) {
        const int k0 = chunk * 32;
        const uint32_t base = sb + s * 4 * TILE_B;
        for (int idx = tid; idx < 512; idx += 256) {
            const int r = idx >> 2, c = idx & 3;
            const uint32_t dst = (uint32_t)(r * 5 + c) * 16;
            const int ar = n0 + r;
            const int av = (ar < Nrows);
            const size_t ao = (size_t)(av ? ar : 0) * 1024 + k0 + c * 8;
            cp16(base + dst,              Ah + ao, av);
            cp16(base + TILE_B + dst,     Al + ao, av);
            const size_t wo = (size_t)(m0 + r) * 1024 + k0 + c * 8;
            cp16(base + 2*TILE_B + dst,   Wh + wo, 1);
            cp16(base + 3*TILE_B + dst,   Wl + wo, 1);
        }
    };

    float acc[4][4][4];
#pragma unroll
    for (int i = 0; i < 4; i++)
#pragma unroll
        for (int j = 0; j < 4; j++)
#pragma unroll
            for (int d = 0; d < 4; d++) acc[i][j][d] = 0.f;

    const int rA = warp_m * 64 + (lane & 15);
    const int rW = warp_n * 32 + (lane & 15);

    fill(0, 0); CP_COMMIT();

    for (int ch = 0; ch < 32; ch++) {
        if (ch + 1 < 32) { fill(ch + 1, (ch + 1) & 1); CP_COMMIT(); CP_WAIT1(); }
        else             { CP_WAIT0(); }
        __syncthreads();

        const uint32_t base = sb + (ch & 1) * 4 * TILE_B;
        const uint32_t aHb = base, aLb = base + TILE_B;
        const uint32_t wHb = base + 2*TILE_B, wLb = base + 3*TILE_B;

#pragma unroll
        for (int ks = 0; ks < 2; ks++) {
            const int c16 = ks * 2 + (lane >> 4);
            uint32_t ah[4][4], al[4][4], bh[2][4], bl[2][4];
#pragma unroll
            for (int ma = 0; ma < 4; ma++) {
                const uint32_t off = (uint32_t)((rA + ma*16) * 5 + c16) * 16;
                LDM4(ah[ma], aHb + off);
                LDM4(al[ma], aLb + off);
            }
#pragma unroll
            for (int nb = 0; nb < 2; nb++) {
                const uint32_t off = (uint32_t)((rW + nb*16) * 5 + c16) * 16;
                LDM4(bh[nb], wHb + off);
                LDM4(bl[nb], wLb + off);
            }
#pragma unroll
            for (int ma = 0; ma < 4; ma++)
#pragma unroll
                for (int n8 = 0; n8 < 4; n8++) {
                    const int nb = n8 >> 1, h = n8 & 1;
                    MMA16816(acc[ma][n8], ah[ma], bh[nb][0+h], bh[nb][2+h]);
                    MMA16816(acc[ma][n8], ah[ma], bl[nb][0+h], bl[nb][2+h]);
                    MMA16816(acc[ma][n8], al[ma], bh[nb][0+h], bh[nb][2+h]);
                }
        }
        __syncthreads();
    }

    float bias2[4][2];
#pragma unroll
    for (int n8 = 0; n8 < 4; n8++) {
        const int m = m0 + warp_n*32 + n8*8 + (lane & 3)*2;
        bias2[n8][0] = bias[m];
        bias2[n8][1] = bias[m + 1];
    }
#pragma unroll
    for (int ma = 0; ma < 4; ma++)
#pragma unroll
        for (int half = 0; half < 2; half++) {
            const int n = n0 + warp_m*64 + ma*16 + (lane >> 2) + half*8;
            if (n >= Nrows) continue;
#pragma unroll
            for (int n8 = 0; n8 < 4; n8++) {
                const int m = m0 + warp_n*32 + n8*8 + (lane & 3)*2;
                float vx = acc[ma][n8][2*half + 0] + bias2[n8][0];
                float vy = acc[ma][n8][2*half + 1] + bias2[n8][1];
                if (MODE == 0) {
                    vx *= scale; vy *= scale;
                    const int b = n / Ss, s = n - b * Ss;
                    const int h = m >> 6, d = m & 63;
                    const size_t off = (((size_t)(b*NH_ + h))*Ss + s)*DH_ + d;
                    *(uint32_t*)(outh + off) = pack_bf16(vx, vy);
                    *(uint32_t*)(outl + off) = pack_bf16(bf16_res(vx), bf16_res(vy));
                } else {
                    float2 v; v.x = vx; v.y = vy;
                    *(float2*)(outf + (size_t)n*1024 + m) = v;
                }
            }
        }
}

// ---------------------------------------------------------------------------
// HMMA flash attention. Grid (10, 512), 128 threads (4 warps x 16 q rows).
// Split-bf16 3-pass for QK^T and PV. Multiplicative mask (ref semantics).
// Smem rows at 144B pitch ((r*9+c)%8 permutes -> conflict-free ldmatrix).
// ---------------------------------------------------------------------------
#define AP       9                    // 16B units per row
#define ATILE_B  (64*AP*16)           // 9216 B per 64x64 bf16 tile
#define SM_MASK  0
#define SM_Q     2560                 // Qh, Ql
#define SM_KV    (2560 + 2*ATILE_B)   // 2 stages x {Kh,Kl,Vh,Vl}
#define SMEM_ATT (SM_KV + 8*ATILE_B) // 94720 B

__global__ __launch_bounds__(128, 1)
void attn_mma(const float* __restrict__ mask,
              __nv_bfloat16* __restrict__ Ch, __nv_bfloat16* __restrict__ Cl)
{
    extern __shared__ __align__(128) char smem[];
    const uint32_t sb = smem_u32(smem);
    float* mask_s = (float*)smem;

    const int bh = blockIdx.y;
    const int b = bh >> 4, h = bh & 15;
    const int q0 = blockIdx.x * 64;
    const int tid = threadIdx.x;
    const int wid = tid >> 5;
    const int lane = tid & 31;

    const __nv_bfloat16* Qhg = g_Qh + (size_t)bh * Ss * DH_;
    const __nv_bfloat16* Qlg = g_Ql + (size_t)bh * Ss * DH_;
    const __nv_bfloat16* Khg = g_Kh + (size_t)bh * Ss * DH_;
    const __nv_bfloat16* Klg = g_Kl + (size_t)bh * Ss * DH_;
    const __nv_bfloat16* Vhg = g_Vh + (size_t)bh * Ss * DH_;
    const __nv_bfloat16* Vlg = g_Vl + (size_t)bh * Ss * DH_;

    // mask row -> smem (zero-padded to 640)
    for (int i = tid; i < 640; i += 128)
        mask_s[i] = (i < Ss) ? mask[b * Ss + i] : 0.f;

    // Q tiles (once)
    for (int idx = tid; idx < 512; idx += 128) {
        const int r = idx >> 3, c = idx & 7;
        const uint32_t dst = (uint32_t)(r * AP + c) * 16;
        const int q = q0 + r;
        const int v = (q < Ss);
        const size_t off = (size_t)(v ? q : 0) * 64 + c * 8;
        cp16(sb + SM_Q + dst,           Qhg + off, v);
        cp16(sb + SM_Q + ATILE_B + dst, Qlg + off, v);
    }

    auto fillKV = [&](int kt, int s) {
        const int k0 = kt * 64;
        const uint32_t base = sb + SM_KV + s * 4 * ATILE_B;
        for (int idx = tid; idx < 512; idx += 128) {
            const int r = idx >> 3, c = idx & 7;
            const uint32_t dst = (uint32_t)(r * AP + c) * 16;
            const int k = k0 + r;
            const int v = (k < Ss);
            const size_t off = (size_t)(v ? k : 0) * 64 + c * 8;
            cp16(base + dst,             Khg + off, v);
            cp16(base + ATILE_B + dst,   Klg + off, v);
            cp16(base + 2*ATILE_B + dst, Vhg + off, v);
            cp16(base + 3*ATILE_B + dst, Vlg + off, v);
        }
    };

    fillKV(0, 0); CP_COMMIT();

    float m0v = -1e30f, m1v = -1e30f, l0 = 0.f, l1 = 0.f;
    float ctx[8][4];
#pragma unroll
    for (int i = 0; i < 8; i++)
#pragma unroll
        for (int j = 0; j < 4; j++) ctx[i][j] = 0.f;

    const int rQ = wid * 16 + (lane & 15);
    const int hi16 = lane >> 4;

    for (int kt = 0; kt < 10; kt++) {
        __syncthreads();   // stage being overwritten fully consumed
        if (kt + 1 < 10) { fillKV(kt + 1, (kt + 1) & 1); CP_COMMIT(); CP_WAIT1(); }
        else             { CP_WAIT0(); }
        __syncthreads();

        const uint32_t base = sb + SM_KV + (kt & 1) * 4 * ATILE_B;
        const uint32_t kHb = base, kLb = base + ATILE_B;
        const uint32_t vHb = base + 2*ATILE_B, vLb = base + 3*ATILE_B;

        // ---- scores = Q . K^T (3-pass split) ----
        float s[8][4];
#pragma unroll
        for (int i = 0; i < 8; i++)
#pragma unroll
            for (int j = 0; j < 4; j++) s[i][j] = 0.f;

#pragma unroll
        for (int kk = 0; kk < 4; kk++) {
            const int c16 = kk * 2 + hi16;
            uint32_t qh[4], ql[4];
            const uint32_t qoff = (uint32_t)(rQ * AP + c16) * 16;
            LDM4(qh, sb + SM_Q + qoff);
            LDM4(ql, sb + SM_Q + ATILE_B + qoff);
#pragma unroll
            for (int nb = 0; nb < 4; nb++) {
                uint32_t kh[4], kl[4];
                const uint32_t koff = (uint32_t)((nb*16 + (lane & 15)) * AP + c16) * 16;
                LDM4(kh, kHb + koff);
                LDM4(kl, kLb + koff);
#pragma unroll
                for (int hh = 0; hh < 2; hh++) {
                    MMA16816(s[2*nb+hh], qh, kh[0+hh], kh[2+hh]);
                    MMA16816(s[2*nb+hh], qh, kl[0+hh], kl[2+hh]);
                    MMA16816(s[2*nb+hh], ql, kh[0+hh], kh[2+hh]);
                }
            }
        }

        // ---- multiplicative mask + key padding ----
        const int k0 = kt * 64;
#pragma unroll
        for (int n8 = 0; n8 < 8; n8++) {
            const int kb = k0 + n8*8 + 2*(lane & 3);
            const float mA = mask_s[kb], mB = mask_s[kb + 1];
            const bool okA = (kb < Ss), okB = (kb + 1 < Ss);
            s[n8][0] = okA ? s[n8][0]*mA : -1e30f;
            s[n8][1] = okB ? s[n8][1]*mB : -1e30f;
            s[n8][2] = okA ? s[n8][2]*mA : -1e30f;
            s[n8][3] = okB ? s[n8][3]*mB : -1e30f;
        }

        // ---- online softmax (rows r0=lane>>2, r1=r0+8; reduce over lane&3) ----
        float tm0 = -1e30f, tm1 = -1e30f;
#pragma unroll
        for (int n8 = 0; n8 < 8; n8++) {
            tm0 = fmaxf(tm0, fmaxf(s[n8][0], s[n8][1]));
            tm1 = fmaxf(tm1, fmaxf(s[n8][2], s[n8][3]));
        }
#pragma unroll
        for (int o = 1; o <= 2; o <<= 1) {
            tm0 = fmaxf(tm0, __shfl_xor_sync(0xffffffffu, tm0, o));
            tm1 = fmaxf(tm1, __shfl_xor_sync(0xffffffffu, tm1, o));
        }
        const float mn0 = fmaxf(m0v, tm0), mn1 = fmaxf(m1v, tm1);
        const float c0 = __expf(m0v - mn0), c1 = __expf(m1v - mn1);
        float rs0 = 0.f, rs1 = 0.f;
#pragma unroll
        for (int n8 = 0; n8 < 8; n8++) {
            s[n8][0] = __expf(s[n8][0] - mn0); rs0 += s[n8][0];
            s[n8][1] = __expf(s[n8][1] - mn0); rs0 += s[n8][1];
            s[n8][2] = __expf(s[n8][2] - mn1); rs1 += s[n8][2];
            s[n8][3] = __expf(s[n8][3] - mn1); rs1 += s[n8][3];
        }
#pragma unroll
        for (int o = 1; o <= 2; o <<= 1) {
            rs0 += __shfl_xor_sync(0xffffffffu, rs0, o);
            rs1 += __shfl_xor_sync(0xffffffffu, rs1, o);
        }
        l0 = l0*c0 + rs0; l1 = l1*c1 + rs1;
        m0v = mn0; m1v = mn1;
#pragma unroll
        for (int n8 = 0; n8 < 8; n8++) {
            ctx[n8][0] *= c0; ctx[n8][1] *= c0;
            ctx[n8][2] *= c1; ctx[n8][3] *= c1;
        }

        // ---- ctx += P @ V (3-pass split; P frags reused from s regs) ----
#pragma unroll
        for (int t = 0; t < 4; t++) {
            uint32_t ph[4], pl[4];
            ph[0] = pack_bf16(s[2*t][0],   s[2*t][1]);
            ph[1] = pack_bf16(s[2*t][2],   s[2*t][3]);
            ph[2] = pack_bf16(s[2*t+1][0], s[2*t+1][1]);
            ph[3] = pack_bf16(s[2*t+1][2], s[2*t+1][3]);
            pl[0] = pack_bf16(bf16_res(s[2*t][0]),   bf16_res(s[2*t][1]));
            pl[1] = pack_bf16(bf16_res(s[2*t][2]),   bf16_res(s[2*t][3]));
            pl[2] = pack_bf16(bf16_res(s[2*t+1][0]), bf16_res(s[2*t+1][1]));
            pl[3] = pack_bf16(bf16_res(s[2*t+1][2]), bf16_res(s[2*t+1][3]));
#pragma unroll
            for (int g = 0; g < 4; g++) {
                uint32_t vh[4], vl[4];
                const uint32_t voff = (uint32_t)((t*16 + (lane & 15)) * AP + g*2 + hi16) * 16;
                LDM4T(vh, vHb + voff);
                LDM4T(vl, vLb + voff);
#pragma unroll
                for (int hh = 0; hh < 2; hh++) {
                    MMA16816(ctx[2*g+hh], ph, vh[2*hh], vh[2*hh+1]);
                    MMA16816(ctx[2*g+hh], ph, vl[2*hh], vl[2*hh+1]);
                    MMA16816(ctx[2*g+hh], pl, vh[2*hh], vh[2*hh+1]);
                }
            }
        }
    }

    // ---- epilogue: bf16 hi/lo token-major [B,S,H] ----
    const float i0 = 1.f / l0, i1 = 1.f / l1;
    const int qr = q0 + wid*16 + (lane >> 2);
    const int d0 = 2*(lane & 3);
#pragma unroll
    for (int n8 = 0; n8 < 8; n8++) {
        const int d = h*64 + n8*8 + d0;
        if (qr < Ss) {
            const float vx = ctx[n8][0]*i0, vy = ctx[n8][1]*i0;
            const size_t off = ((size_t)(b*Ss + qr))*Hh + d;
            *(uint32_t*)(Ch + off) = pack_bf16(vx, vy);
            *(uint32_t*)(Cl + off) = pack_bf16(bf16_res(vx), bf16_res(vy));
        }
        if (qr + 8 < Ss) {
            const float vx = ctx[n8][2]*i1, vy = ctx[n8][3]*i1;
            const size_t off = ((size_t)(b*Ss + qr + 8))*Hh + d;
            *(uint32_t*)(Ch + off) = pack_bf16(vx, vy);
            *(uint32_t*)(Cl + off) = pack_bf16(bf16_res(vx), bf16_res(vy));
        }
    }
}

// ---------------------------------------------------------------------------
extern "C" void kernel_launch(void* const* d_in, const int* in_sizes, int n_in,
                              void* d_out, int out_size)
{
    const float* X    = (const float*)d_in[0];
    const float* mask = (const float*)d_in[1];
    const float* Wq   = (const float*)d_in[2];
    const float* bq   = (const float*)d_in[3];
    const float* Wk   = (const float*)d_in[4];
    const float* bk   = (const float*)d_in[5];
    const float* Wv   = (const float*)d_in[6];
    const float* bv   = (const float*)d_in[7];
    const float* Wo   = (const float*)d_in[8];
    const float* bo   = (const float*)d_in[9];
    float* out = (float*)d_out;

    __nv_bfloat16 *Xh, *Xl, *Wh, *Wl, *Qh, *Ql, *Kh, *Kl, *Vh, *Vl, *Ch, *Cl;
    cudaGetSymbolAddress((void**)&Xh, g_Xh);
    cudaGetSymbolAddress((void**)&Xl, g_Xl);
    cudaGetSymbolAddress((void**)&Wh, g_Wh);
    cudaGetSymbolAddress((void**)&Wl, g_Wl);
    cudaGetSymbolAddress((void**)&Qh, g_Qh);
    cudaGetSymbolAddress((void**)&Ql, g_Ql);
    cudaGetSymbolAddress((void**)&Kh, g_Kh);
    cudaGetSymbolAddress((void**)&Kl, g_Kl);
    cudaGetSymbolAddress((void**)&Vh, g_Vh);
    cudaGetSymbolAddress((void**)&Vl, g_Vl);
    cudaGetSymbolAddress((void**)&Ch, g_Ch);
    cudaGetSymbolAddress((void**)&Cl, g_Cl);

    static bool attr_done = false;
    if (!attr_done) {
        cudaFuncSetAttribute(gemm_mma<0>, cudaFuncAttributeMaxDynamicSharedMemorySize, SMEM_GEMM);
        cudaFuncSetAttribute(gemm_mma<1>, cudaFuncAttributeMaxDynamicSharedMemorySize, SMEM_GEMM);
        cudaFuncSetAttribute(attn_mma, cudaFuncAttributeMaxDynamicSharedMemorySize, SMEM_ATT);
        attr_done = true;
    }

    // split inputs to bf16 hi/lo
    split_k<<<NTOK, 256>>>(X, Xh, Xl, NTOK * Hh);
    const float* Ws[4] = {Wq, Wk, Wv, Wo};
    for (int w = 0; w < 4; w++)
        split_k<<<1024, 256>>>(Ws[w], Wh + (size_t)w*Hh*Hh, Wl + (size_t)w*Hh*Hh, Hh*Hh);

    const dim3 gg((NTOK + 127) / 128, Hh / 128);
    // Q pre-scaled by 1/sqrt(DH)=0.125
    gemm_mma<0><<<gg, 256, SMEM_GEMM>>>(Xh, Xl, Wh + 0*(size_t)Hh*Hh, Wl + 0*(size_t)Hh*Hh,
                                        bq, Qh, Ql, nullptr, 0.125f, NTOK);
    gemm_mma<0><<<gg, 256, SMEM_GEMM>>>(Xh, Xl, Wh + 1*(size_t)Hh*Hh, Wl + 1*(size_t)Hh*Hh,
                                        bk, Kh, Kl, nullptr, 1.0f, NTOK);
    gemm_mma<0><<<gg, 256, SMEM_GEMM>>>(Xh, Xl, Wh + 2*(size_t)Hh*Hh, Wl + 2*(size_t)Hh*Hh,
                                        bv, Vh, Vl, nullptr, 1.0f, NTOK);

    attn_mma<<<dim3((Ss + 63) / 64, Bb * NH_), 128, SMEM_ATT>>>(mask, Ch, Cl);

    gemm_mma<1><<<gg, 256, SMEM_GEMM>>>(Ch, Cl, Wh + 3*(size_t)Hh*Hh, Wl + 3*(size_t)Hh*Hh,
                                        bo, nullptr, nullptr, out, 1.0f, NTOK);
}